// round 16
// baseline (speedup 1.0000x reference)
#include <cuda_runtime.h>
#include <cuda_fp16.h>
#include <cstdint>
#include <cstddef>

#define THREADS 256
#define MAX_NODES 50176

// scratch (no cudaMalloc allowed)
__device__ float g_den[MAX_NODES];
__device__ unsigned int g_done;

// ---------------- smem layout (bytes) ----------------
#define OFF_FLAG 0
#define OFF_B1   128      // 64 f
#define OFF_B2   384      // 64 f
#define OFF_CF   640      // 64 f
#define OFF_SRC  896      // 128 i32
#define OFF_DEST 1408     // 128 i32
#define OFF_IRAW 1920     // 2048  raw edge_list stage (int64: 16B/edge)
#define OFF_XHI  4096     // 128 x 72 fp16 = 18432 (row stride 144B)
#define OFF_XLO  22528    // 18432
#define OFF_W1HI 40960    // 64 x 72 fp16 = 9216  (W[k][n], row stride 144B)
#define OFF_W2HI 50176    // 9216
#define OFF_W2LO 59392    // 9216
#define OFF_XRAW 68608    // 128 x 64 f32 = 32768 raw x stage (cp.async dst)
#define SMEM_BYTES 101376

__device__ __forceinline__ uint32_t smem_u32(const void* p) {
    uint32_t a;
    asm("{ .reg .u64 t; cvta.to.shared.u64 t, %1; cvt.u32.u64 %0, t; }"
        : "=r"(a) : "l"(p));
    return a;
}

// fast tanh: sign(x) * (1 - 2e/(1+e)), e = exp(-2|x|)  (rel err ~1e-6)
__device__ __forceinline__ float ftanh(float x) {
    float ax = fabsf(x);
    float e;
    asm("ex2.approx.f32 %0, %1;" : "=f"(e) : "f"(ax * -2.8853900817779268f));
    float r;
    asm("rcp.approx.f32 %0, %1;" : "=f"(r) : "f"(e + 1.0f));
    float t = fmaf(-2.0f * e, r, 1.0f);
    return __uint_as_float(__float_as_uint(t) | (__float_as_uint(x) & 0x80000000u));
}

// pack two floats to fp16x2 in ONE instruction (first arg -> low half)
__device__ __forceinline__ uint32_t pack2h(float lo_v, float hi_v) {
    uint32_t r;
    asm("cvt.rn.f16x2.f32 %0, %1, %2;" : "=r"(r) : "f"(hi_v), "f"(lo_v));
    return r;
}
__device__ __forceinline__ float h_hi(float v) {   // round-trip fp16 value
    return __half2float(__float2half_rn(v));
}

__device__ __forceinline__ void ldsm_x4(uint32_t* a, uint32_t addr) {
    asm volatile("ldmatrix.sync.aligned.m8n8.x4.shared.b16 {%0,%1,%2,%3}, [%4];"
                 : "=r"(a[0]), "=r"(a[1]), "=r"(a[2]), "=r"(a[3]) : "r"(addr));
}
__device__ __forceinline__ void ldsm_x4t(uint32_t* b, uint32_t addr) {
    asm volatile("ldmatrix.sync.aligned.m8n8.x4.trans.shared.b16 {%0,%1,%2,%3}, [%4];"
                 : "=r"(b[0]), "=r"(b[1]), "=r"(b[2]), "=r"(b[3]) : "r"(addr));
}
__device__ __forceinline__ void mma16816(float* c, const uint32_t* a,
                                         uint32_t b0, uint32_t b1) {
    asm volatile("mma.sync.aligned.m16n8k16.row.col.f32.f16.f16.f32 "
                 "{%0,%1,%2,%3}, {%4,%5,%6,%7}, {%8,%9}, {%0,%1,%2,%3};"
                 : "+f"(c[0]), "+f"(c[1]), "+f"(c[2]), "+f"(c[3])
                 : "r"(a[0]), "r"(a[1]), "r"(a[2]), "r"(a[3]), "r"(b0), "r"(b1));
}

// ---------- cp.async ----------
__device__ __forceinline__ void cpa16(uint32_t dst, const void* src, int szbytes) {
    asm volatile("cp.async.cg.shared.global [%0], [%1], 16, %2;"
                 :: "r"(dst), "l"(src), "r"(szbytes));
}
__device__ __forceinline__ void cpa8(uint32_t dst, const void* src, int szbytes) {
    asm volatile("cp.async.ca.shared.global [%0], [%1], 8, %2;"
                 :: "r"(dst), "l"(src), "r"(szbytes));
}
__device__ __forceinline__ void cpa_commit() { asm volatile("cp.async.commit_group;"); }
__device__ __forceinline__ void cpa_wait0()  { asm volatile("cp.async.wait_group 0;"); }

// issue staged loads for tile at 'base'
__device__ __forceinline__ void stage_tile(uint32_t sbase, const float* edge_emb,
                                           const char* elist, int base, int nE,
                                           bool is32, int tid)
{
    // raw x: 128 rows x 64 floats
    #pragma unroll
    for (int f0 = 0; f0 < 8; f0++) {
        int f = tid + f0 * THREADS;
        int rr = f >> 4, q = f & 15;
        int e = base + rr;
        cpa16(sbase + OFF_XRAW + (uint32_t)(rr * 256 + q * 16),
              edge_emb + (size_t)e * 64 + q * 4, e < nE ? 16 : 0);
    }
    // raw indices
    if (tid < 128) {
        int e = base + tid;
        if (is32)
            cpa8(sbase + OFF_IRAW + tid * 8, elist + (size_t)e * 8,
                 e < nE ? 8 : 0);
        else
            cpa16(sbase + OFF_IRAW + tid * 16, elist + (size_t)e * 16,
                  e < nE ? 16 : 0);
    }
}

__global__ __launch_bounds__(THREADS, 2)
void cfconv_tc(const float* __restrict__ atom_emb,
               const float* __restrict__ edge_emb,
               const float* __restrict__ W1, const float* __restrict__ b1,
               const float* __restrict__ W2, const float* __restrict__ b2,
               const float* __restrict__ coef,
               const void*  __restrict__ edge_list,
               float* __restrict__ num, int nE, int total4)
{
    extern __shared__ unsigned char s[];
    const uint32_t sbase = smem_u32(s);

    float* b1s    = (float*)(s + OFF_B1);
    float* b2s    = (float*)(s + OFF_B2);
    float* cfs    = (float*)(s + OFF_CF);
    int*   src_s  = (int*)(s + OFF_SRC);
    int*   dest_s = (int*)(s + OFF_DEST);
    int*   flag_s = (int*)(s + OFF_FLAG);

    const int tid  = threadIdx.x;
    const int wid  = tid >> 5;
    const int lane = tid & 31;
    const int m0   = wid * 16;           // this warp's 16-edge strip in the 128-tile

    if (tid == 0) *flag_s = 0;

    // ---- W tables (fp16): W1 hi only (2-term exact-x GEMM1); W2 hi+lo ----
    for (int idx = tid; idx < 4096; idx += THREADS) {
        int k = idx >> 6, n = idx & 63;
        uint32_t off = (uint32_t)(k * 72 + n) * 2;
        *(__half*)(s + OFF_W1HI + off) = __float2half_rn(W1[idx]);
        float v2 = W2[idx];
        float h2 = h_hi(v2);
        *(__half*)(s + OFF_W2HI + off) = __float2half_rn(v2);
        *(__half*)(s + OFF_W2LO + off) = __float2half_rn(v2 - h2);
    }
    if (tid < 64) { b1s[tid] = b1[tid]; b2s[tid] = b2[tid]; cfs[tid] = coef[tid]; }
    __syncthreads();

    // edge_list dtype detect: int64 => odd 32-bit words all zero
    {
        const int* ei = (const int*)edge_list;
        if (tid < 64 && ei[2 * tid + 1] != 0) atomicOr(flag_s, 1);
    }
    __syncthreads();
    const bool is32 = (*flag_s != 0);
    const char* elist = (const char*)edge_list;

    // fragment geometry
    const int r    = lane >> 2;          // row-in-8
    const int cgrp = lane & 3;
    const int cb   = cgrp * 2;           // column pair base
    const int l15  = lane & 15;

    // ldmatrix base addresses
    const uint32_t aAddrHi = sbase + OFF_XHI
        + (uint32_t)(m0 + l15) * 144 + (uint32_t)(lane >> 4) * 16;
    const uint32_t aAddrLo = aAddrHi + (OFF_XLO - OFF_XHI);
    // B addresses: lanes 0-15 -> n-tile jp*2, lanes 16-31 -> n-tile jp*2+1
    const uint32_t bAddr = (uint32_t)l15 * 144 + (uint32_t)(lane >> 4) * 16;
    const uint32_t w1h = sbase + OFF_W1HI + bAddr;
    const uint32_t w2h = sbase + OFF_W2HI + bAddr;
    const uint32_t w2l = sbase + OFF_W2LO + bAddr;

    const int nTiles = (nE + 127) >> 7;
    const int stride = gridDim.x;

    // prologue: stage first tile
    int t0 = blockIdx.x;
    if (t0 < nTiles)
        stage_tile(sbase, edge_emb, elist, t0 << 7, nE, is32, tid);
    cpa_commit();

    for (int t = t0; t < nTiles; t += stride) {
        const int base = t << 7;
        cpa_wait0();
        __syncthreads();   // staged raw visible; prev tile fully done

        // ---- parse 128 edge indices from staged raw ----
        if (tid < 128) {
            int d = 0, sr = 0;
            if (base + tid < nE) {
                if (is32) { int2 p = *(const int2*)(s + OFF_IRAW + tid * 8); d = p.x; sr = p.y; }
                else { longlong2 p = *(const longlong2*)(s + OFF_IRAW + tid * 16); d = (int)p.x; sr = (int)p.y; }
            }
            dest_s[tid] = d; src_s[tid] = sr;
        }

        // ---- convert staged raw -> fp16 hi/lo tiles (pure smem traffic) ----
        #pragma unroll
        for (int f0 = 0; f0 < 8; f0++) {
            int f = tid + f0 * THREADS;          // 0..2047
            int rr = f >> 4, q = f & 15;
            float4 v = *(const float4*)(s + OFF_XRAW + rr * 256 + q * 16);
            float h0 = h_hi(v.x), h1 = h_hi(v.y), h2 = h_hi(v.z), h3 = h_hi(v.w);
            uint32_t off = (uint32_t)rr * 144 + (uint32_t)q * 8;
            uint2 hi2 = make_uint2(pack2h(v.x, v.y), pack2h(v.z, v.w));
            uint2 lo2 = make_uint2(pack2h(v.x - h0, v.y - h1),
                                   pack2h(v.z - h2, v.w - h3));
            *(uint2*)(s + OFF_XHI + off) = hi2;
            *(uint2*)(s + OFF_XLO + off) = lo2;
        }
        __syncthreads();   // hi/lo + indices ready; raw stage consumable

        // ---- stage next tile (overlaps with GEMMs + epilogue) ----
        int tn = t + stride;
        if (tn < nTiles)
            stage_tile(sbase, edge_emb, elist, tn << 7, nE, is32, tid);
        cpa_commit();

        // ---- GEMM1: acc = (xhi + xlo) @ W1hi  (exact-x 2-term) ----
        float acc[8][4];
        #pragma unroll
        for (int j = 0; j < 8; j++)
            acc[j][0] = acc[j][1] = acc[j][2] = acc[j][3] = 0.f;

        #pragma unroll
        for (int kk = 0; kk < 4; kk++) {
            uint32_t Ah[4], Al[4];
            ldsm_x4(Ah, aAddrHi + kk * 32);
            ldsm_x4(Al, aAddrLo + kk * 32);
            #pragma unroll
            for (int jp = 0; jp < 4; jp++) {
                uint32_t Bh[4];
                ldsm_x4t(Bh, w1h + kk * 2304 + jp * 32);
                mma16816(acc[2 * jp],     Ah, Bh[0], Bh[1]);
                mma16816(acc[2 * jp],     Al, Bh[0], Bh[1]);
                mma16816(acc[2 * jp + 1], Ah, Bh[2], Bh[3]);
                mma16816(acc[2 * jp + 1], Al, Bh[2], Bh[3]);
            }
        }

        // ---- GEMM2 fused with tanh: per-kk A2 slice; 3-term split ----
        float acc2[8][4];
        #pragma unroll
        for (int j = 0; j < 8; j++)
            acc2[j][0] = acc2[j][1] = acc2[j][2] = acc2[j][3] = 0.f;

        #pragma unroll
        for (int kk = 0; kk < 4; kk++) {
            // build A2 fragment slice for k-tile kk from acc[2kk], acc[2kk+1]
            uint32_t A2h[4], A2l[4];
            #pragma unroll
            for (int jj = 0; jj < 2; jj++) {
                int j = 2 * kk + jj;
                float bb0 = b1s[cb + 8 * j], bb1 = b1s[cb + 8 * j + 1];
                float t0f = ftanh(acc[j][0] + bb0);
                float t1f = ftanh(acc[j][1] + bb1);
                float t2f = ftanh(acc[j][2] + bb0);
                float t3f = ftanh(acc[j][3] + bb1);
                float h0 = h_hi(t0f), h1 = h_hi(t1f), h2 = h_hi(t2f), h3 = h_hi(t3f);
                A2h[jj * 2]     = pack2h(t0f, t1f);
                A2h[jj * 2 + 1] = pack2h(t2f, t3f);
                A2l[jj * 2]     = pack2h(t0f - h0, t1f - h1);
                A2l[jj * 2 + 1] = pack2h(t2f - h2, t3f - h3);
            }
            #pragma unroll
            for (int jp = 0; jp < 4; jp++) {
                uint32_t Bh[4], Bl[4];
                ldsm_x4t(Bh, w2h + kk * 2304 + jp * 32);
                ldsm_x4t(Bl, w2l + kk * 2304 + jp * 32);
                mma16816(acc2[2 * jp],     A2h, Bh[0], Bh[1]);
                mma16816(acc2[2 * jp],     A2h, Bl[0], Bl[1]);
                mma16816(acc2[2 * jp],     A2l, Bh[0], Bh[1]);
                mma16816(acc2[2 * jp + 1], A2h, Bh[2], Bh[3]);
                mma16816(acc2[2 * jp + 1], A2h, Bl[2], Bl[3]);
                mma16816(acc2[2 * jp + 1], A2l, Bh[2], Bh[3]);
            }
        }

        // ---- epilogue: gather once (held in regs), attn dot, scatter ----
        const int row0 = m0 + r, row1 = m0 + r + 8;
        const int e0 = base + row0, e1 = base + row1;
        const int s0 = src_s[row0], s1 = src_s[row1];
        const int d0 = dest_s[row0], d1 = dest_s[row1];
        const float* g0p = atom_emb + (size_t)s0 * 64 + cb;
        const float* g1p = atom_emb + (size_t)s1 * 64 + cb;

        float2 ga[8], gb[8];
        float p0 = 0.f, p1 = 0.f;
        #pragma unroll
        for (int j = 0; j < 8; j++) {
            int col = cb + 8 * j;
            ga[j] = *(const float2*)(g0p + 8 * j);
            gb[j] = *(const float2*)(g1p + 8 * j);
            float bb0 = b2s[col], bb1 = b2s[col + 1];
            // fold bias into acc2 so scatter needs no reload
            acc2[j][0] += bb0; acc2[j][1] += bb1;
            acc2[j][2] += bb0; acc2[j][3] += bb1;
            float c0 = cfs[col], c1 = cfs[col + 1];
            p0 = fmaf(ga[j].x * acc2[j][0], c0, fmaf(ga[j].y * acc2[j][1], c1, p0));
            p1 = fmaf(gb[j].x * acc2[j][2], c0, fmaf(gb[j].y * acc2[j][3], c1, p1));
        }
        // reduce across the 4 lanes sharing each row
        p0 += __shfl_xor_sync(0xffffffffu, p0, 1);
        p0 += __shfl_xor_sync(0xffffffffu, p0, 2);
        p1 += __shfl_xor_sync(0xffffffffu, p1, 1);
        p1 += __shfl_xor_sync(0xffffffffu, p1, 2);
        float a0 = __expf(p0), a1 = __expf(p1);

        if (cgrp == 0) {
            if (e0 < nE) atomicAdd(&g_den[d0], a0);
            if (e1 < nE) atomicAdd(&g_den[d1], a1);
        }
        // ---- scatter from held registers (no gather reload) ----
        if (e0 < nE) {
            float* dst = num + (size_t)d0 * 64 + cb;
            #pragma unroll
            for (int j = 0; j < 8; j++) {
                float mx = ga[j].x * acc2[j][0] * a0;
                float my = ga[j].y * acc2[j][1] * a0;
                asm volatile("red.global.add.v2.f32 [%0], {%1,%2};"
                             :: "l"(dst + 8 * j), "f"(mx), "f"(my) : "memory");
            }
        }
        if (e1 < nE) {
            float* dst = num + (size_t)d1 * 64 + cb;
            #pragma unroll
            for (int j = 0; j < 8; j++) {
                float mx = gb[j].x * acc2[j][2] * a1;
                float my = gb[j].y * acc2[j][3] * a1;
                asm volatile("red.global.add.v2.f32 [%0], {%1,%2};"
                             :: "l"(dst + 8 * j), "f"(mx), "f"(my) : "memory");
            }
        }
    }

    // ================= fused division epilogue =================
    // Grid-wide sync: all 296 CTAs are co-resident (2/SM, 148+ SMs), so a
    // counter barrier is deadlock-free. RED/atomics above are ordered by
    // the release-fence before the arrive.
    __syncthreads();
    __threadfence();
    if (tid == 0) {
        unsigned int total = gridDim.x;
        asm volatile("red.release.gpu.global.add.u32 [%0], 1;"
                     :: "l"(&g_done) : "memory");
        unsigned int v;
        do {
            asm volatile("ld.acquire.gpu.global.u32 %0, [%1];"
                         : "=r"(v) : "l"(&g_done) : "memory");
            if (v >= total) break;
            __nanosleep(256);
        } while (true);
    }
    __syncthreads();

    // out[i] /= den where den > 0 (L2-warm: RED results + g_den resident)
    float4* out4 = (float4*)num;
    for (int i = blockIdx.x * THREADS + tid; i < total4; i += gridDim.x * THREADS) {
        float den = g_den[i >> 4];
        float4 v = out4[i];
        if (den > 0.f) {
            float rcp = 1.0f / den;
            v.x *= rcp; v.y *= rcp; v.z *= rcp; v.w *= rcp;
        }
        out4[i] = v;
    }
}

extern "C" void kernel_launch(void* const* d_in, const int* in_sizes, int n_in,
                              void* d_out, int out_size)
{
    const float* atom_emb = (const float*)d_in[0];
    const float* edge_emb = (const float*)d_in[1];
    const float* W1       = (const float*)d_in[2];
    const float* b1       = (const float*)d_in[3];
    const float* W2       = (const float*)d_in[4];
    const float* b2       = (const float*)d_in[5];
    const float* coef     = (const float*)d_in[6];
    const void*  elist    = d_in[7];
    float* out = (float*)d_out;

    int nE     = in_sizes[1] / 64;
    int nNodes = in_sizes[0] / 64;
    int total4 = out_size / 4;

    // zero num (d_out), den, and the grid-sync counter (graph-capturable)
    cudaMemsetAsync(d_out, 0, (size_t)out_size * sizeof(float), 0);
    void* denp = nullptr;
    cudaGetSymbolAddress(&denp, g_den);
    cudaMemsetAsync(denp, 0, (size_t)nNodes * sizeof(float), 0);
    void* donep = nullptr;
    cudaGetSymbolAddress(&donep, g_done);
    cudaMemsetAsync(donep, 0, sizeof(unsigned int), 0);

    cudaFuncSetAttribute(cfconv_tc, cudaFuncAttributeMaxDynamicSharedMemorySize,
                         SMEM_BYTES);
    // grid 296 = single persistent co-resident wave (2 CTAs/SM); division
    // epilogue fused via grid-wide counter barrier (removes cfconv_div launch).
    cfconv_tc<<<296, THREADS, SMEM_BYTES, 0>>>(atom_emb, edge_emb, W1, b1, W2, b2,
                                               coef, elist, out, nE, total4);
}

// round 17
// speedup vs baseline: 1.5023x; 1.5023x over previous
#include <cuda_runtime.h>
#include <cuda_fp16.h>
#include <cstdint>
#include <cstddef>

#define THREADS 256
#define MAX_NODES 50176

// scratch (no cudaMalloc allowed)
__device__ float g_den[MAX_NODES];

// ---------------- smem layout (bytes) ----------------
#define OFF_FLAG 0
#define OFF_B1   128      // 64 f
#define OFF_B2   384      // 64 f
#define OFF_CF   640      // 64 f
#define OFF_SRC  896      // 128 i32
#define OFF_DEST 1408     // 128 i32
#define OFF_IRAW 1920     // 2048  raw edge_list stage (int64: 16B/edge)
#define OFF_XHI  4096     // 128 x 72 fp16 = 18432 (row stride 144B)
#define OFF_XLO  22528    // 18432
#define OFF_W1HI 40960    // 64 x 72 fp16 = 9216  (W[k][n], row stride 144B)
#define OFF_W2HI 50176    // 9216
#define OFF_W2LO 59392    // 9216
#define OFF_XRAW 68608    // 128 x 64 f32 = 32768 raw x stage (cp.async dst)
#define SMEM_BYTES 101376

__device__ __forceinline__ uint32_t smem_u32(const void* p) {
    uint32_t a;
    asm("{ .reg .u64 t; cvta.to.shared.u64 t, %1; cvt.u32.u64 %0, t; }"
        : "=r"(a) : "l"(p));
    return a;
}

// fast tanh: sign(x) * (1 - 2e/(1+e)), e = exp(-2|x|)  (rel err ~1e-6)
__device__ __forceinline__ float ftanh(float x) {
    float ax = fabsf(x);
    float e;
    asm("ex2.approx.f32 %0, %1;" : "=f"(e) : "f"(ax * -2.8853900817779268f));
    float r;
    asm("rcp.approx.f32 %0, %1;" : "=f"(r) : "f"(e + 1.0f));
    float t = fmaf(-2.0f * e, r, 1.0f);
    return __uint_as_float(__float_as_uint(t) | (__float_as_uint(x) & 0x80000000u));
}

// pack two floats to fp16x2 in ONE instruction (first arg -> low half)
__device__ __forceinline__ uint32_t pack2h(float lo_v, float hi_v) {
    uint32_t r;
    asm("cvt.rn.f16x2.f32 %0, %1, %2;" : "=r"(r) : "f"(hi_v), "f"(lo_v));
    return r;
}
__device__ __forceinline__ float h_hi(float v) {   // round-trip fp16 value
    return __half2float(__float2half_rn(v));
}

__device__ __forceinline__ void ldsm_x4(uint32_t* a, uint32_t addr) {
    asm volatile("ldmatrix.sync.aligned.m8n8.x4.shared.b16 {%0,%1,%2,%3}, [%4];"
                 : "=r"(a[0]), "=r"(a[1]), "=r"(a[2]), "=r"(a[3]) : "r"(addr));
}
__device__ __forceinline__ void ldsm_x4t(uint32_t* b, uint32_t addr) {
    asm volatile("ldmatrix.sync.aligned.m8n8.x4.trans.shared.b16 {%0,%1,%2,%3}, [%4];"
                 : "=r"(b[0]), "=r"(b[1]), "=r"(b[2]), "=r"(b[3]) : "r"(addr));
}
__device__ __forceinline__ void mma16816(float* c, const uint32_t* a,
                                         uint32_t b0, uint32_t b1) {
    asm volatile("mma.sync.aligned.m16n8k16.row.col.f32.f16.f16.f32 "
                 "{%0,%1,%2,%3}, {%4,%5,%6,%7}, {%8,%9}, {%0,%1,%2,%3};"
                 : "+f"(c[0]), "+f"(c[1]), "+f"(c[2]), "+f"(c[3])
                 : "r"(a[0]), "r"(a[1]), "r"(a[2]), "r"(a[3]), "r"(b0), "r"(b1));
}

// ---------- cp.async ----------
__device__ __forceinline__ void cpa16(uint32_t dst, const void* src, int szbytes) {
    asm volatile("cp.async.cg.shared.global [%0], [%1], 16, %2;"
                 :: "r"(dst), "l"(src), "r"(szbytes));
}
__device__ __forceinline__ void cpa8(uint32_t dst, const void* src, int szbytes) {
    asm volatile("cp.async.ca.shared.global [%0], [%1], 8, %2;"
                 :: "r"(dst), "l"(src), "r"(szbytes));
}
__device__ __forceinline__ void cpa_commit() { asm volatile("cp.async.commit_group;"); }
__device__ __forceinline__ void cpa_wait0()  { asm volatile("cp.async.wait_group 0;"); }

// issue staged loads for tile at 'base'
__device__ __forceinline__ void stage_tile(uint32_t sbase, const float* edge_emb,
                                           const char* elist, int base, int nE,
                                           bool is32, int tid)
{
    // raw x: 128 rows x 64 floats
    #pragma unroll
    for (int f0 = 0; f0 < 8; f0++) {
        int f = tid + f0 * THREADS;
        int rr = f >> 4, q = f & 15;
        int e = base + rr;
        cpa16(sbase + OFF_XRAW + (uint32_t)(rr * 256 + q * 16),
              edge_emb + (size_t)e * 64 + q * 4, e < nE ? 16 : 0);
    }
    // raw indices
    if (tid < 128) {
        int e = base + tid;
        if (is32)
            cpa8(sbase + OFF_IRAW + tid * 8, elist + (size_t)e * 8,
                 e < nE ? 8 : 0);
        else
            cpa16(sbase + OFF_IRAW + tid * 16, elist + (size_t)e * 16,
                  e < nE ? 16 : 0);
    }
}

__global__ __launch_bounds__(THREADS, 2)
void cfconv_tc(const float* __restrict__ atom_emb,
               const float* __restrict__ edge_emb,
               const float* __restrict__ W1, const float* __restrict__ b1,
               const float* __restrict__ W2, const float* __restrict__ b2,
               const float* __restrict__ coef,
               const void*  __restrict__ edge_list,
               float* __restrict__ num, int nE)
{
    extern __shared__ unsigned char s[];
    const uint32_t sbase = smem_u32(s);

    float* b1s    = (float*)(s + OFF_B1);
    float* b2s    = (float*)(s + OFF_B2);
    float* cfs    = (float*)(s + OFF_CF);
    int*   src_s  = (int*)(s + OFF_SRC);
    int*   dest_s = (int*)(s + OFF_DEST);
    int*   flag_s = (int*)(s + OFF_FLAG);

    const int tid  = threadIdx.x;
    const int wid  = tid >> 5;
    const int lane = tid & 31;
    const int m0   = wid * 16;           // this warp's 16-edge strip in the 128-tile

    if (tid == 0) *flag_s = 0;

    // ---- W tables (fp16): W1 hi only (2-term exact-x GEMM1); W2 hi+lo ----
    for (int idx = tid; idx < 4096; idx += THREADS) {
        int k = idx >> 6, n = idx & 63;
        uint32_t off = (uint32_t)(k * 72 + n) * 2;
        *(__half*)(s + OFF_W1HI + off) = __float2half_rn(W1[idx]);
        float v2 = W2[idx];
        float h2 = h_hi(v2);
        *(__half*)(s + OFF_W2HI + off) = __float2half_rn(v2);
        *(__half*)(s + OFF_W2LO + off) = __float2half_rn(v2 - h2);
    }
    if (tid < 64) { b1s[tid] = b1[tid]; b2s[tid] = b2[tid]; cfs[tid] = coef[tid]; }
    __syncthreads();

    // edge_list dtype detect: int64 => odd 32-bit words all zero
    {
        const int* ei = (const int*)edge_list;
        if (tid < 64 && ei[2 * tid + 1] != 0) atomicOr(flag_s, 1);
    }
    __syncthreads();
    const bool is32 = (*flag_s != 0);
    const char* elist = (const char*)edge_list;

    // fragment geometry
    const int r    = lane >> 2;          // row-in-8
    const int cgrp = lane & 3;
    const int cb   = cgrp * 2;           // column pair base
    const int l15  = lane & 15;

    // ldmatrix base addresses
    const uint32_t aAddrHi = sbase + OFF_XHI
        + (uint32_t)(m0 + l15) * 144 + (uint32_t)(lane >> 4) * 16;
    const uint32_t aAddrLo = aAddrHi + (OFF_XLO - OFF_XHI);
    // B addresses: lanes 0-15 -> n-tile jp*2, lanes 16-31 -> n-tile jp*2+1
    const uint32_t bAddr = (uint32_t)l15 * 144 + (uint32_t)(lane >> 4) * 16;
    const uint32_t w1h = sbase + OFF_W1HI + bAddr;
    const uint32_t w2h = sbase + OFF_W2HI + bAddr;
    const uint32_t w2l = sbase + OFF_W2LO + bAddr;

    const int nTiles = (nE + 127) >> 7;
    const int stride = gridDim.x;

    // prologue: stage first tile
    int t0 = blockIdx.x;
    if (t0 < nTiles)
        stage_tile(sbase, edge_emb, elist, t0 << 7, nE, is32, tid);
    cpa_commit();

    for (int t = t0; t < nTiles; t += stride) {
        const int base = t << 7;
        cpa_wait0();
        __syncthreads();   // staged raw visible; prev tile fully done

        // ---- parse 128 edge indices from staged raw ----
        if (tid < 128) {
            int d = 0, sr = 0;
            if (base + tid < nE) {
                if (is32) { int2 p = *(const int2*)(s + OFF_IRAW + tid * 8); d = p.x; sr = p.y; }
                else { longlong2 p = *(const longlong2*)(s + OFF_IRAW + tid * 16); d = (int)p.x; sr = (int)p.y; }
            }
            dest_s[tid] = d; src_s[tid] = sr;
        }

        // ---- convert staged raw -> fp16 hi/lo tiles (pure smem traffic) ----
        #pragma unroll
        for (int f0 = 0; f0 < 8; f0++) {
            int f = tid + f0 * THREADS;          // 0..2047
            int rr = f >> 4, q = f & 15;
            float4 v = *(const float4*)(s + OFF_XRAW + rr * 256 + q * 16);
            float h0 = h_hi(v.x), h1 = h_hi(v.y), h2 = h_hi(v.z), h3 = h_hi(v.w);
            uint32_t off = (uint32_t)rr * 144 + (uint32_t)q * 8;
            uint2 hi2 = make_uint2(pack2h(v.x, v.y), pack2h(v.z, v.w));
            uint2 lo2 = make_uint2(pack2h(v.x - h0, v.y - h1),
                                   pack2h(v.z - h2, v.w - h3));
            *(uint2*)(s + OFF_XHI + off) = hi2;
            *(uint2*)(s + OFF_XLO + off) = lo2;
        }
        __syncthreads();   // hi/lo + indices ready; raw stage consumable

        // ---- stage next tile (overlaps with GEMMs + epilogue) ----
        int tn = t + stride;
        if (tn < nTiles)
            stage_tile(sbase, edge_emb, elist, tn << 7, nE, is32, tid);
        cpa_commit();

        // ---- GEMM1: acc = (xhi + xlo) @ W1hi  (exact-x 2-term) ----
        float acc[8][4];
        #pragma unroll
        for (int j = 0; j < 8; j++)
            acc[j][0] = acc[j][1] = acc[j][2] = acc[j][3] = 0.f;

        #pragma unroll
        for (int kk = 0; kk < 4; kk++) {
            uint32_t Ah[4], Al[4];
            ldsm_x4(Ah, aAddrHi + kk * 32);
            ldsm_x4(Al, aAddrLo + kk * 32);
            #pragma unroll
            for (int jp = 0; jp < 4; jp++) {
                uint32_t Bh[4];
                ldsm_x4t(Bh, w1h + kk * 2304 + jp * 32);
                mma16816(acc[2 * jp],     Ah, Bh[0], Bh[1]);
                mma16816(acc[2 * jp],     Al, Bh[0], Bh[1]);
                mma16816(acc[2 * jp + 1], Ah, Bh[2], Bh[3]);
                mma16816(acc[2 * jp + 1], Al, Bh[2], Bh[3]);
            }
        }

        // ---- GEMM2 fused with tanh: per-kk A2 slice; 3-term split ----
        float acc2[8][4];
        #pragma unroll
        for (int j = 0; j < 8; j++)
            acc2[j][0] = acc2[j][1] = acc2[j][2] = acc2[j][3] = 0.f;

        #pragma unroll
        for (int kk = 0; kk < 4; kk++) {
            // build A2 fragment slice for k-tile kk from acc[2kk], acc[2kk+1]
            uint32_t A2h[4], A2l[4];
            #pragma unroll
            for (int jj = 0; jj < 2; jj++) {
                int j = 2 * kk + jj;
                float bb0 = b1s[cb + 8 * j], bb1 = b1s[cb + 8 * j + 1];
                float t0f = ftanh(acc[j][0] + bb0);
                float t1f = ftanh(acc[j][1] + bb1);
                float t2f = ftanh(acc[j][2] + bb0);
                float t3f = ftanh(acc[j][3] + bb1);
                float h0 = h_hi(t0f), h1 = h_hi(t1f), h2 = h_hi(t2f), h3 = h_hi(t3f);
                A2h[jj * 2]     = pack2h(t0f, t1f);
                A2h[jj * 2 + 1] = pack2h(t2f, t3f);
                A2l[jj * 2]     = pack2h(t0f - h0, t1f - h1);
                A2l[jj * 2 + 1] = pack2h(t2f - h2, t3f - h3);
            }
            #pragma unroll
            for (int jp = 0; jp < 4; jp++) {
                uint32_t Bh[4], Bl[4];
                ldsm_x4t(Bh, w2h + kk * 2304 + jp * 32);
                ldsm_x4t(Bl, w2l + kk * 2304 + jp * 32);
                mma16816(acc2[2 * jp],     A2h, Bh[0], Bh[1]);
                mma16816(acc2[2 * jp],     A2h, Bl[0], Bl[1]);
                mma16816(acc2[2 * jp],     A2l, Bh[0], Bh[1]);
                mma16816(acc2[2 * jp + 1], A2h, Bh[2], Bh[3]);
                mma16816(acc2[2 * jp + 1], A2h, Bl[2], Bl[3]);
                mma16816(acc2[2 * jp + 1], A2l, Bh[2], Bh[3]);
            }
        }

        // ---- epilogue: gather once (held in regs), attn dot, scatter ----
        const int row0 = m0 + r, row1 = m0 + r + 8;
        const int e0 = base + row0, e1 = base + row1;
        const int s0 = src_s[row0], s1 = src_s[row1];
        const int d0 = dest_s[row0], d1 = dest_s[row1];
        const float* g0p = atom_emb + (size_t)s0 * 64 + cb;
        const float* g1p = atom_emb + (size_t)s1 * 64 + cb;

        float2 ga[8], gb[8];
        float p0 = 0.f, p1 = 0.f;
        #pragma unroll
        for (int j = 0; j < 8; j++) {
            int col = cb + 8 * j;
            ga[j] = *(const float2*)(g0p + 8 * j);
            gb[j] = *(const float2*)(g1p + 8 * j);
            float bb0 = b2s[col], bb1 = b2s[col + 1];
            // fold bias into acc2 so scatter needs no reload
            acc2[j][0] += bb0; acc2[j][1] += bb1;
            acc2[j][2] += bb0; acc2[j][3] += bb1;
            float c0 = cfs[col], c1 = cfs[col + 1];
            p0 = fmaf(ga[j].x * acc2[j][0], c0, fmaf(ga[j].y * acc2[j][1], c1, p0));
            p1 = fmaf(gb[j].x * acc2[j][2], c0, fmaf(gb[j].y * acc2[j][3], c1, p1));
        }
        // reduce across the 4 lanes sharing each row
        p0 += __shfl_xor_sync(0xffffffffu, p0, 1);
        p0 += __shfl_xor_sync(0xffffffffu, p0, 2);
        p1 += __shfl_xor_sync(0xffffffffu, p1, 1);
        p1 += __shfl_xor_sync(0xffffffffu, p1, 2);
        float a0 = __expf(p0), a1 = __expf(p1);

        if (cgrp == 0) {
            if (e0 < nE) atomicAdd(&g_den[d0], a0);
            if (e1 < nE) atomicAdd(&g_den[d1], a1);
        }
        // ---- scatter from held registers (no gather reload) ----
        if (e0 < nE) {
            float* dst = num + (size_t)d0 * 64 + cb;
            #pragma unroll
            for (int j = 0; j < 8; j++) {
                float mx = ga[j].x * acc2[j][0] * a0;
                float my = ga[j].y * acc2[j][1] * a0;
                asm volatile("red.global.add.v2.f32 [%0], {%1,%2};"
                             :: "l"(dst + 8 * j), "f"(mx), "f"(my) : "memory");
            }
        }
        if (e1 < nE) {
            float* dst = num + (size_t)d1 * 64 + cb;
            #pragma unroll
            for (int j = 0; j < 8; j++) {
                float mx = gb[j].x * acc2[j][2] * a1;
                float my = gb[j].y * acc2[j][3] * a1;
                asm volatile("red.global.add.v2.f32 [%0], {%1,%2};"
                             :: "l"(dst + 8 * j), "f"(mx), "f"(my) : "memory");
            }
        }
    }
}

__global__ void cfconv_div(float4* __restrict__ out, int total4)
{
    int i = blockIdx.x * blockDim.x + threadIdx.x;
    if (i < total4) {
        float den = g_den[i >> 4];
        float4 v = out[i];
        if (den > 0.f) {
            float r = 1.0f / den;
            v.x *= r; v.y *= r; v.z *= r; v.w *= r;
        }
        out[i] = v;
    }
}

extern "C" void kernel_launch(void* const* d_in, const int* in_sizes, int n_in,
                              void* d_out, int out_size)
{
    const float* atom_emb = (const float*)d_in[0];
    const float* edge_emb = (const float*)d_in[1];
    const float* W1       = (const float*)d_in[2];
    const float* b1       = (const float*)d_in[3];
    const float* W2       = (const float*)d_in[4];
    const float* b2       = (const float*)d_in[5];
    const float* coef     = (const float*)d_in[6];
    const void*  elist    = d_in[7];
    float* out = (float*)d_out;

    int nE     = in_sizes[1] / 64;
    int nNodes = in_sizes[0] / 64;
    int total4 = out_size / 4;

    // zero num (d_out) and den via driver memsets (cheap, not kernel launches)
    cudaMemsetAsync(d_out, 0, (size_t)out_size * sizeof(float), 0);
    void* denp = nullptr;
    cudaGetSymbolAddress(&denp, g_den);
    cudaMemsetAsync(denp, 0, (size_t)nNodes * sizeof(float), 0);

    cudaFuncSetAttribute(cfconv_tc, cudaFuncAttributeMaxDynamicSharedMemorySize,
                         SMEM_BYTES);
    // grid 296 = single persistent wave of 2 CTAs/SM — the measured optimum
    // (R11/R14/R15). R12 (occupancy restructure), R13 (two waves) and R16
    // (fused division epilogue -> register spills) all measured worse.
    cfconv_tc<<<296, THREADS, SMEM_BYTES, 0>>>(atom_emb, edge_emb, W1, b1, W2, b2,
                                               coef, elist, out, nE);

    cfconv_div<<<(total4 + 255) / 256, 256>>>((float4*)out, total4);
}